// round 17
// baseline (speedup 1.0000x reference)
#include <cuda_runtime.h>
#include <cuda_bf16.h>
#include <math.h>
#include <stdint.h>

// Problem constants
constexpr int BATCH = 8192;
constexpr int DIM   = 512;
constexpr int K8    = 8;
constexpr float INV_TAU = 5.0f;
constexpr float ALPHA   = 0.3f;
constexpr float LN_EPS  = 1e-5f;

// GEMM tiling (R8/R16 proven): CTA 128x256, BK=64, empty-mbarrier bulk pipeline
constexpr int BM = 128, BN = 256, BK = 64;
constexpr int KCH = DIM / BK;
constexpr int BLKE = 128 * 64;
constexpr int BLKB = 16384;
constexpr int STAGE = 6 * BLKB;
constexpr int SMEM_DYN = 1024 + 2 * STAGE;   // 197632; epilogue tile 128*257*4=131584 fits

constexpr int NTILE = BATCH / BN;   // 32 col-tiles
constexpr int MTILE = BATCH / BM;   // 64 row-tiles
constexpr int RSLOT = NTILE * 2;    // 64 row-partial slots per row
constexpr int CSLOT = MTILE;        // 64 col-partial slots per col

// ---------------- scratch ----------------
__device__ __nv_bfloat16 g_gi_h[BATCH * DIM], g_gi_l[BATCH * DIM];
__device__ __nv_bfloat16 g_gt_h[BATCH * DIM], g_gt_l[BATCH * DIM];
__device__ __nv_bfloat16 g_gIr_h[BATCH * DIM], g_gIr_l[BATCH * DIM];
__device__ __nv_bfloat16 g_gTr_h[BATCH * DIM], g_gTr_l[BATCH * DIM];
__device__ __nv_bfloat16 g_Wi_h[DIM * DIM], g_Wi_l[DIM * DIM];
__device__ __nv_bfloat16 g_Wt_h[DIM * DIM], g_Wt_l[DIM * DIM];
__device__ float g_PT[BATCH * DIM];
__device__ float g_PI[BATCH * DIM];
__device__ float g_rowW[BATCH * K8];
__device__ int   g_rowI[BATCH * K8];
__device__ float g_colW[BATCH * K8];
__device__ int   g_colI[BATCH * K8];
__device__ float g_rpV[(size_t)BATCH * RSLOT * K8];
__device__ int   g_rpI[(size_t)BATCH * RSLOT * K8];
__device__ float g_cpV[(size_t)BATCH * CSLOT * K8];
__device__ int   g_cpI[(size_t)BATCH * CSLOT * K8];

// ---------------- PTX helpers ----------------
__device__ __forceinline__ uint32_t smem_u32(const void* p) {
    return (uint32_t)__cvta_generic_to_shared(p);
}
__device__ __forceinline__ void ldsm4(uint32_t* r, uint32_t a) {
    asm volatile("ldmatrix.sync.aligned.m8n8.x4.shared.b16 {%0,%1,%2,%3}, [%4];"
                 : "=r"(r[0]), "=r"(r[1]), "=r"(r[2]), "=r"(r[3]) : "r"(a));
}
__device__ __forceinline__ void mma_bf16(float* c, const uint32_t* a,
                                         uint32_t b0, uint32_t b1) {
    asm volatile("mma.sync.aligned.m16n8k16.row.col.f32.bf16.bf16.f32 "
                 "{%0,%1,%2,%3}, {%4,%5,%6,%7}, {%8,%9}, {%0,%1,%2,%3};"
                 : "+f"(c[0]), "+f"(c[1]), "+f"(c[2]), "+f"(c[3])
                 : "r"(a[0]), "r"(a[1]), "r"(a[2]), "r"(a[3]), "r"(b0), "r"(b1));
}
__device__ __forceinline__ void mbar_init(uint32_t a, uint32_t cnt) {
    asm volatile("mbarrier.init.shared.b64 [%0], %1;" :: "r"(a), "r"(cnt) : "memory");
}
__device__ __forceinline__ void mbar_expect(uint32_t a, uint32_t bytes) {
    asm volatile("mbarrier.arrive.expect_tx.shared.b64 _, [%0], %1;"
                 :: "r"(a), "r"(bytes) : "memory");
}
__device__ __forceinline__ void mbar_arrive(uint32_t a) {
    asm volatile("mbarrier.arrive.release.cta.shared::cta.b64 _, [%0];" :: "r"(a) : "memory");
}
__device__ __forceinline__ void mbar_wait(uint32_t a, uint32_t parity) {
    uint32_t done;
    asm volatile("{\n\t.reg .pred p;\n\t"
                 "mbarrier.try_wait.parity.acquire.cta.shared::cta.b64 p, [%1], %2;\n\t"
                 "selp.b32 %0, 1, 0, p;\n\t}" : "=r"(done) : "r"(a), "r"(parity) : "memory");
    if (!done) {
        asm volatile("{\n\t.reg .pred P1;\n\t"
                     "W_%=:\n\t"
                     "mbarrier.try_wait.parity.acquire.cta.shared::cta.b64 P1, [%0], %1, 0x989680;\n\t"
                     "@P1 bra.uni D_%=;\n\t"
                     "bra.uni W_%=;\n\t"
                     "D_%=:\n\t}" :: "r"(a), "r"(parity) : "memory");
    }
}
__device__ __forceinline__ void bulk_cp(uint32_t dst, const void* src, uint32_t bytes,
                                        uint32_t mbar) {
    asm volatile("cp.async.bulk.shared::cta.global.mbarrier::complete_tx::bytes "
                 "[%0], [%1], %2, [%3];"
                 :: "r"(dst), "l"(__cvta_generic_to_global(src)), "r"(bytes), "r"(mbar)
                 : "memory");
}

// ---------------- split-bf16 GEMM + fused topk partials ----------------
__global__ void __launch_bounds__(256, 1)
gemm_mma(const __nv_bfloat16* __restrict__ Ah, const __nv_bfloat16* __restrict__ Al,
         const __nv_bfloat16* __restrict__ Bh, const __nv_bfloat16* __restrict__ Bl,
         float* __restrict__ C, int ldc, float alpha, int do_topk)
{
    extern __shared__ char smem[];
    const uint32_t sb = smem_u32(smem);
    const uint32_t mb  = sb;
    const uint32_t emb = sb + 16;
    const uint32_t bufb = (sb + 1024u) & ~1023u;
    const int tid = threadIdx.x, wid = tid >> 5, lane = tid & 31;
    const int wm = wid >> 2, wn = wid & 3;
    const int bm = blockIdx.y * BM, bn = blockIdx.x * BN;
    const int g = lane >> 3, r8 = lane & 7;

    uint32_t abase[4], bbase[4];
#pragma unroll
    for (int i = 0; i < 4; i++) {
        int row = wm * 64 + i * 16 + r8 + (g & 1) * 8;
        abase[i] = (uint32_t)(row * 128);
    }
#pragma unroll
    for (int j = 0; j < 4; j++) {
        int row = wn * 64 + j * 16 + r8 + (g >> 1) * 8;
        bbase[j] = (uint32_t)((row & 127) * 128 + (row >> 7) * BLKB);
    }
    const uint32_t acsel = (uint32_t)((g >> 1) * 16);
    const uint32_t bcsel = (uint32_t)((g & 1) * 16);

    float acc[4][8][4];
#pragma unroll
    for (int i = 0; i < 4; i++)
#pragma unroll
        for (int j = 0; j < 8; j++)
#pragma unroll
            for (int q = 0; q < 4; q++) acc[i][j][q] = 0.0f;

    auto arm_load = [&](int s, int kc) {
        uint32_t mbar = mb + (uint32_t)s * 8;
        mbar_expect(mbar, STAGE);
        uint32_t st = bufb + (uint32_t)s * STAGE;
        size_t a  = ((size_t)((bm >> 7) * KCH + kc)) * BLKE;
        size_t b0 = ((size_t)((bn >> 7) * KCH + kc)) * BLKE;
        size_t b1 = ((size_t)(((bn >> 7) + 1) * KCH + kc)) * BLKE;
        bulk_cp(st,             Ah + a,  BLKB, mbar);
        bulk_cp(st + BLKB,      Al + a,  BLKB, mbar);
        bulk_cp(st + 2 * BLKB,  Bh + b0, BLKB, mbar);
        bulk_cp(st + 3 * BLKB,  Bh + b1, BLKB, mbar);
        bulk_cp(st + 4 * BLKB,  Bl + b0, BLKB, mbar);
        bulk_cp(st + 5 * BLKB,  Bl + b1, BLKB, mbar);
    };

    if (tid == 0) {
        mbar_init(mb, 1);    mbar_init(mb + 8, 1);
        mbar_init(emb, 256); mbar_init(emb + 8, 256);
    }
    __syncthreads();
    if (tid == 0) { arm_load(0, 0); arm_load(1, 1); }

    for (int t = 0; t < KCH; t++) {
        const int s = t & 1;
        mbar_wait(mb + (uint32_t)s * 8, (t >> 1) & 1);
        const uint32_t st = bufb + (uint32_t)s * STAGE;

#pragma unroll
        for (int ks = 0; ks < 4; ks++) {
            const uint32_t ac = acsel + ks * 32;
            const uint32_t bc = bcsel + ks * 32;
            uint32_t Afr[4][4], Alf[4][4], Bhf[4][4], Blf[4][4];
#pragma unroll
            for (int i = 0; i < 4; i++) {
                uint32_t o = abase[i] + ac; o ^= (o >> 3) & 0x70;
                ldsm4(Afr[i], st + o);
            }
#pragma unroll
            for (int j = 0; j < 4; j++) {
                uint32_t o = bbase[j] + bc; o ^= (o >> 3) & 0x70;
                ldsm4(Bhf[j], st + 2 * BLKB + o);
            }
#pragma unroll
            for (int i = 0; i < 4; i++) {
                uint32_t o = abase[i] + ac; o ^= (o >> 3) & 0x70;
                ldsm4(Alf[i], st + BLKB + o);
            }
#pragma unroll
            for (int j = 0; j < 4; j++) {
                uint32_t o = bbase[j] + bc; o ^= (o >> 3) & 0x70;
                ldsm4(Blf[j], st + 4 * BLKB + o);
            }
#pragma unroll
            for (int i = 0; i < 4; i++)
#pragma unroll
                for (int j = 0; j < 4; j++) {
                    mma_bf16(acc[i][2 * j],     Afr[i], Bhf[j][0], Bhf[j][1]);
                    mma_bf16(acc[i][2 * j + 1], Afr[i], Bhf[j][2], Bhf[j][3]);
                }
#pragma unroll
            for (int i = 0; i < 4; i++)
#pragma unroll
                for (int j = 0; j < 4; j++) {
                    mma_bf16(acc[i][2 * j],     Alf[i], Bhf[j][0], Bhf[j][1]);
                    mma_bf16(acc[i][2 * j + 1], Alf[i], Bhf[j][2], Bhf[j][3]);
                }
#pragma unroll
            for (int i = 0; i < 4; i++)
#pragma unroll
                for (int j = 0; j < 4; j++) {
                    mma_bf16(acc[i][2 * j],     Afr[i], Blf[j][0], Blf[j][1]);
                    mma_bf16(acc[i][2 * j + 1], Afr[i], Blf[j][2], Blf[j][3]);
                }
        }

        if (t + 2 < KCH) {
            mbar_arrive(emb + (uint32_t)s * 8);
            if (tid == 0) {
                mbar_wait(emb + (uint32_t)s * 8, (t >> 1) & 1);
                arm_load(s, t + 2);
            }
        }
    }

    // global stores (unchanged)
    const int row0 = bm + wm * 64 + (lane >> 2);
    const int col0 = bn + wn * 64 + (lane & 3) * 2;
#pragma unroll
    for (int i = 0; i < 4; i++) {
#pragma unroll
        for (int j = 0; j < 8; j++) {
            int r = row0 + i * 16, cc = col0 + j * 8;
            float2 v0 = make_float2(acc[i][j][0] * alpha, acc[i][j][1] * alpha);
            float2 v1 = make_float2(acc[i][j][2] * alpha, acc[i][j][3] * alpha);
            *(float2*)&C[(size_t)r * ldc + cc]       = v0;
            *(float2*)&C[(size_t)(r + 8) * ldc + cc] = v1;
        }
    }

    if (!do_topk) return;

    // ---- fused topk partials: stage tile to smem, scan rows + cols ----
    float* ep = reinterpret_cast<float*>(smem);    // 128 x 257 floats
    __syncthreads();   // all warps done with stage buffers / mbarriers

    const int rl0 = wm * 64 + (lane >> 2);
    const int cl0 = wn * 64 + (lane & 3) * 2;
#pragma unroll
    for (int i = 0; i < 4; i++) {
#pragma unroll
        for (int j = 0; j < 8; j++) {
            int rl = rl0 + i * 16, cl = cl0 + j * 8;
            ep[rl * 257 + cl]           = acc[i][j][0] * alpha;
            ep[rl * 257 + cl + 1]       = acc[i][j][1] * alpha;
            ep[(rl + 8) * 257 + cl]     = acc[i][j][2] * alpha;
            ep[(rl + 8) * 257 + cl + 1] = acc[i][j][3] * alpha;
        }
    }
    __syncthreads();

    // row partials: 2 threads per row, 128-col half-segments
    {
        const int rr = tid >> 1, half = tid & 1;
        const float* rp = ep + rr * 257 + half * 128;
        const int gc0 = bn + half * 128;
        float tv[K8]; int ti_[K8];
#pragma unroll
        for (int t = 0; t < K8; t++) { tv[t] = -1e30f; ti_[t] = 0; }
        for (int c = 0; c < 128; c += 4) {
            float a0 = rp[c], a1 = rp[c + 1], a2 = rp[c + 2], a3 = rp[c + 3];
            float m4 = fmaxf(fmaxf(a0, a1), fmaxf(a2, a3));
            if (m4 > tv[0]) {
                float vals[4] = {a0, a1, a2, a3};
#pragma unroll
                for (int e = 0; e < 4; e++) {
                    float x = vals[e];
                    if (x > tv[0]) {
                        tv[0] = x; ti_[0] = gc0 + c + e;
#pragma unroll
                        for (int q = 0; q < K8 - 1; q++) {
                            if (tv[q] > tv[q + 1]) {
                                float a = tv[q]; tv[q] = tv[q + 1]; tv[q + 1] = a;
                                int b = ti_[q]; ti_[q] = ti_[q + 1]; ti_[q + 1] = b;
                            }
                        }
                    }
                }
            }
        }
        size_t base = (((size_t)(bm + rr)) * RSLOT + ((bn >> 8) * 2 + half)) * K8;
#pragma unroll
        for (int k = 0; k < K8; k++) {
            g_rpV[base + k] = tv[K8 - 1 - k];
            g_rpI[base + k] = ti_[K8 - 1 - k];
        }
    }

    // col partials: 1 thread per col, 128 rows
    {
        const int cc = tid;
        const float* cp = ep + cc;
        float tv[K8]; int ti_[K8];
#pragma unroll
        for (int t = 0; t < K8; t++) { tv[t] = -1e30f; ti_[t] = 0; }
        for (int r = 0; r < 128; r += 4) {
            float a0 = cp[r * 257], a1 = cp[(r + 1) * 257];
            float a2 = cp[(r + 2) * 257], a3 = cp[(r + 3) * 257];
            float m4 = fmaxf(fmaxf(a0, a1), fmaxf(a2, a3));
            if (m4 > tv[0]) {
                float vals[4] = {a0, a1, a2, a3};
#pragma unroll
                for (int e = 0; e < 4; e++) {
                    float x = vals[e];
                    if (x > tv[0]) {
                        tv[0] = x; ti_[0] = bm + r + e;
#pragma unroll
                        for (int q = 0; q < K8 - 1; q++) {
                            if (tv[q] > tv[q + 1]) {
                                float a = tv[q]; tv[q] = tv[q + 1]; tv[q + 1] = a;
                                int b = ti_[q]; ti_[q] = ti_[q + 1]; ti_[q + 1] = b;
                            }
                        }
                    }
                }
            }
        }
        size_t base = (((size_t)(bn + cc)) * CSLOT + (bm >> 7)) * K8;
#pragma unroll
        for (int k = 0; k < K8; k++) {
            g_cpV[base + k] = tv[K8 - 1 - k];
            g_cpI[base + k] = ti_[K8 - 1 - k];
        }
    }
}

// ---------------- merge kernels: partial slots -> top-8 + softmax ----------------
__device__ __forceinline__ void merge_slots_softmax(
    const float* __restrict__ V, const int* __restrict__ I, int nslots,
    float* __restrict__ outW, int* __restrict__ outI)
{
    float tv[K8]; int ti_[K8];
#pragma unroll
    for (int t = 0; t < K8; t++) { tv[t] = -1e30f; ti_[t] = 0; }
    for (int s = 0; s < nslots; s++) {
        const float* sv = V + s * K8;
        if (sv[0] <= tv[0]) continue;      // slot max can't insert -> none can
        const int* si = I + s * K8;
#pragma unroll
        for (int k = 0; k < K8; k++) {
            float v = sv[k];
            if (v <= tv[0]) break;         // descending -> rest can't insert
            tv[0] = v; ti_[0] = si[k];
#pragma unroll
            for (int q = 0; q < K8 - 1; q++) {
                if (tv[q] > tv[q + 1]) {
                    float a = tv[q]; tv[q] = tv[q + 1]; tv[q + 1] = a;
                    int b = ti_[q]; ti_[q] = ti_[q + 1]; ti_[q + 1] = b;
                }
            }
        }
    }
    float mx = tv[K8 - 1];
    float w[K8]; float ssum = 0.0f;
#pragma unroll
    for (int j = 0; j < K8; j++) { w[j] = expf(tv[K8 - 1 - j] - mx); ssum += w[j]; }
    float inv = 1.0f / ssum;
#pragma unroll
    for (int j = 0; j < K8; j++) {
        outW[j] = w[j] * inv;
        outI[j] = ti_[K8 - 1 - j];
    }
}

__global__ void row_merge_softmax() {
    int row = blockIdx.x * blockDim.x + threadIdx.x;
    merge_slots_softmax(g_rpV + (size_t)row * RSLOT * K8,
                        g_rpI + (size_t)row * RSLOT * K8, RSLOT,
                        g_rowW + row * K8, g_rowI + row * K8);
}
__global__ void col_merge_softmax2() {
    int col = blockIdx.x * blockDim.x + threadIdx.x;
    merge_slots_softmax(g_cpV + (size_t)col * CSLOT * K8,
                        g_cpI + (size_t)col * CSLOT * K8, CSLOT,
                        g_colW + col * K8, g_colI + col * K8);
}

// ---------------- conversions ----------------
__device__ __forceinline__ void split_bf16(float x, __nv_bfloat16& h, __nv_bfloat16& l) {
    h = __float2bfloat16_rn(x);
    l = __float2bfloat16_rn(x - __bfloat162float(h));
}

__device__ __forceinline__ size_t blk_idx(int row, int u) {
    int rb = row >> 7, kc = u >> 3;
    uint32_t off = (uint32_t)((row & 127) * 128 + (u & 7) * 16);
    off ^= (off >> 3) & 0x70;
    return ((size_t)(rb * KCH + kc)) * BLKE + (off >> 1);
}

__global__ void rownorm_split_kernel(const float* __restrict__ X,
                                     __nv_bfloat16* __restrict__ Yh,
                                     __nv_bfloat16* __restrict__ Yl) {
    __shared__ float sbuf[256];
    __shared__ float rowv[512];
    int row = blockIdx.x, tid = threadIdx.x;
    const float* x = X + (size_t)row * DIM;
    float v0 = x[tid], v1 = x[tid + 256];
    rowv[tid] = v0; rowv[tid + 256] = v1;
    sbuf[tid] = v0 * v0 + v1 * v1;
    __syncthreads();
    for (int s = 128; s > 0; s >>= 1) {
        if (tid < s) sbuf[tid] += sbuf[tid + s];
        __syncthreads();
    }
    float inv = 1.0f / fmaxf(sqrtf(sbuf[0]), 1e-12f);
    if (tid < 128) {
        int u = tid & 63;
        bool hi = tid < 64;
        __nv_bfloat16 out[8];
#pragma unroll
        for (int e = 0; e < 8; e++) {
            float v = rowv[u * 8 + e] * inv;
            __nv_bfloat16 h, l;
            split_bf16(v, h, l);
            out[e] = hi ? h : l;
        }
        size_t idx = blk_idx(row, u);
        *(uint4*)((hi ? Yh : Yl) + idx) = *(uint4*)out;
    }
}

constexpr int NBIG = BATCH * DIM;
constexpr int NW   = DIM * DIM;
constexpr int U_BIG = NBIG / 8;
constexpr int U_W   = NW / 8;
__global__ void split_all_kernel(const float* __restrict__ gI, const float* __restrict__ gT,
                                 const float* __restrict__ Wi, const float* __restrict__ Wt) {
    int gidx = blockIdx.x * blockDim.x + threadIdx.x;
    const float* src; __nv_bfloat16 *H, *L; int unit;
    if (gidx < U_BIG)                { src = gI; H = g_gIr_h; L = g_gIr_l; unit = gidx; }
    else if (gidx < 2 * U_BIG)       { src = gT; H = g_gTr_h; L = g_gTr_l; unit = gidx - U_BIG; }
    else if (gidx < 2 * U_BIG + U_W) { src = Wi; H = g_Wi_h;  L = g_Wi_l;  unit = gidx - 2 * U_BIG; }
    else                             { src = Wt; H = g_Wt_h;  L = g_Wt_l;  unit = gidx - 2 * U_BIG - U_W; }
    int row = unit >> 6, u = unit & 63;
    const float4* s4 = (const float4*)(src + (size_t)row * DIM + u * 8);
    float4 a = s4[0], b = s4[1];
    float vals[8] = {a.x, a.y, a.z, a.w, b.x, b.y, b.z, b.w};
    __nv_bfloat16 h[8], l[8];
#pragma unroll
    for (int e = 0; e < 8; e++) split_bf16(vals[e], h[e], l[e]);
    size_t idx = blk_idx(row, u);
    *(uint4*)(H + idx) = *(uint4*)h;
    *(uint4*)(L + idx) = *(uint4*)l;
}

// ---------------- sparse message + residual + LayerNorm ----------------
__global__ void msg_ln_kernel(const float* __restrict__ X, const float* __restrict__ P,
                              const float* __restrict__ W, const int* __restrict__ IDX,
                              const float* __restrict__ gamma, const float* __restrict__ beta,
                              float* __restrict__ out) {
    __shared__ float sbuf[256];
    __shared__ float sw[K8];
    __shared__ int   sidx[K8];
    const int row = blockIdx.x, tid = threadIdx.x;
    if (tid < K8) { sw[tid] = W[row * K8 + tid]; sidx[tid] = IDX[row * K8 + tid]; }
    __syncthreads();

    float m0 = 0.0f, m1 = 0.0f;
#pragma unroll
    for (int j = 0; j < K8; j++) {
        const float* pr = P + (size_t)sidx[j] * DIM;
        float w = sw[j];
        m0 = fmaf(w, pr[tid], m0);
        m1 = fmaf(w, pr[tid + 256], m1);
    }
    float x0 = X[(size_t)row * DIM + tid]       + ALPHA * m0;
    float x1 = X[(size_t)row * DIM + tid + 256] + ALPHA * m1;

    sbuf[tid] = x0 + x1;
    __syncthreads();
    for (int s = 128; s > 0; s >>= 1) { if (tid < s) sbuf[tid] += sbuf[tid + s]; __syncthreads(); }
    float mu = sbuf[0] * (1.0f / DIM);
    __syncthreads();

    float d0 = x0 - mu, d1 = x1 - mu;
    sbuf[tid] = d0 * d0 + d1 * d1;
    __syncthreads();
    for (int s = 128; s > 0; s >>= 1) { if (tid < s) sbuf[tid] += sbuf[tid + s]; __syncthreads(); }
    float var = sbuf[0] * (1.0f / DIM);
    float rstd = rsqrtf(var + LN_EPS);

    out[(size_t)row * DIM + tid]       = d0 * rstd * gamma[tid]       + beta[tid];
    out[(size_t)row * DIM + tid + 256] = d1 * rstd * gamma[tid + 256] + beta[tid + 256];
}

// ---------------- launch: fully serial ----------------
extern "C" void kernel_launch(void* const* d_in, const int* in_sizes, int n_in,
                              void* d_out, int out_size) {
    const float* gI      = (const float*)d_in[0];
    const float* gT      = (const float*)d_in[1];
    const float* Wi      = (const float*)d_in[2];
    const float* Wt      = (const float*)d_in[3];
    const float* gamma_i = (const float*)d_in[4];
    const float* beta_i  = (const float*)d_in[5];
    const float* gamma_t = (const float*)d_in[6];
    const float* beta_t  = (const float*)d_in[7];

    float* out = (float*)d_out;
    float* gI2 = out;
    float* gT2 = out + (size_t)BATCH * DIM;
    float* S   = out + 2 * (size_t)BATCH * DIM;

    cudaFuncSetAttribute(gemm_mma, cudaFuncAttributeMaxDynamicSharedMemorySize, SMEM_DYN);

    void *p_gi_h, *p_gi_l, *p_gt_h, *p_gt_l;
    void *p_gIr_h, *p_gIr_l, *p_gTr_h, *p_gTr_l;
    void *p_Wi_h, *p_Wi_l, *p_Wt_h, *p_Wt_l;
    void *p_PT, *p_PI, *p_rowW, *p_rowI, *p_colW, *p_colI;
    cudaGetSymbolAddress(&p_gi_h, g_gi_h);   cudaGetSymbolAddress(&p_gi_l, g_gi_l);
    cudaGetSymbolAddress(&p_gt_h, g_gt_h);   cudaGetSymbolAddress(&p_gt_l, g_gt_l);
    cudaGetSymbolAddress(&p_gIr_h, g_gIr_h); cudaGetSymbolAddress(&p_gIr_l, g_gIr_l);
    cudaGetSymbolAddress(&p_gTr_h, g_gTr_h); cudaGetSymbolAddress(&p_gTr_l, g_gTr_l);
    cudaGetSymbolAddress(&p_Wi_h, g_Wi_h);   cudaGetSymbolAddress(&p_Wi_l, g_Wi_l);
    cudaGetSymbolAddress(&p_Wt_h, g_Wt_h);   cudaGetSymbolAddress(&p_Wt_l, g_Wt_l);
    cudaGetSymbolAddress(&p_PT, g_PT);       cudaGetSymbolAddress(&p_PI, g_PI);
    cudaGetSymbolAddress(&p_rowW, g_rowW);   cudaGetSymbolAddress(&p_rowI, g_rowI);
    cudaGetSymbolAddress(&p_colW, g_colW);   cudaGetSymbolAddress(&p_colI, g_colI);

    // (1)(2) normalize + split for S
    rownorm_split_kernel<<<BATCH, 256>>>(gI, (__nv_bfloat16*)p_gi_h, (__nv_bfloat16*)p_gi_l);
    rownorm_split_kernel<<<BATCH, 256>>>(gT, (__nv_bfloat16*)p_gt_h, (__nv_bfloat16*)p_gt_l);

    // (3) S = (gi @ gt^T) / tau, with fused row/col top-8 partials
    gemm_mma<<<dim3(BATCH / BN, BATCH / BM), 256, SMEM_DYN>>>(
        (const __nv_bfloat16*)p_gi_h, (const __nv_bfloat16*)p_gi_l,
        (const __nv_bfloat16*)p_gt_h, (const __nv_bfloat16*)p_gt_l,
        S, BATCH, INV_TAU, 1);

    // (4)(5) merges + softmax   <-- launch 4 profiled by ncu
    row_merge_softmax<<<BATCH / 256, 256>>>();
    col_merge_softmax2<<<BATCH / 256, 256>>>();

    // (6) fused split of gI, gT, Wi, Wt
    constexpr int NTOT = 2 * U_BIG + 2 * U_W;
    split_all_kernel<<<NTOT / 256, 256>>>(gI, gT, Wi, Wt);

    // (7)(8) projections (no topk epilogue)
    gemm_mma<<<dim3(DIM / BN, BATCH / BM), 256, SMEM_DYN>>>(
        (const __nv_bfloat16*)p_gTr_h, (const __nv_bfloat16*)p_gTr_l,
        (const __nv_bfloat16*)p_Wt_h,  (const __nv_bfloat16*)p_Wt_l,
        (float*)p_PT, DIM, 1.0f, 0);
    gemm_mma<<<dim3(DIM / BN, BATCH / BM), 256, SMEM_DYN>>>(
        (const __nv_bfloat16*)p_gIr_h, (const __nv_bfloat16*)p_gIr_l,
        (const __nv_bfloat16*)p_Wi_h,  (const __nv_bfloat16*)p_Wi_l,
        (float*)p_PI, DIM, 1.0f, 0);

    // (9)(10) messages + residual + LayerNorm
    msg_ln_kernel<<<BATCH, 256>>>(gI, (const float*)p_PT, (const float*)p_rowW,
                                  (const int*)p_rowI, gamma_i, beta_i, gI2);
    msg_ln_kernel<<<BATCH, 256>>>(gT, (const float*)p_PI, (const float*)p_colW,
                                  (const int*)p_colI, gamma_t, beta_t, gT2);
}